// round 7
// baseline (speedup 1.0000x reference)
#include <cuda_runtime.h>
#include <cuda_bf16.h>
#include <cstdint>

#define BATCH 512
#define SEQ   1024
#define NT    64
#define NSB   (BATCH * SEQ)
#define SLICE 16

// ---------------- device scratch ----------------
__device__ float g_expT[NT * NT];
__device__ float g_expEnd[NT];
__device__ float g_logz[BATCH];
__device__ float g_score[BATCH];
__device__ unsigned long long g_mask_ptr;
__device__ unsigned long long g_tags_ptr;
__device__ int   g_mask8;
__device__ int   g_tags64;
__device__ unsigned char g_maskb[NSB];
__device__ int           g_tagsi[NSB];

// ---------------- PTX helpers ----------------
__device__ __forceinline__ float ex2f(float x) {
    float r; asm("ex2.approx.ftz.f32 %0, %1;" : "=f"(r) : "f"(x)); return r;
}
__device__ __forceinline__ float lg2f(float x) {
    float r; asm("lg2.approx.ftz.f32 %0, %1;" : "=f"(r) : "f"(x)); return r;
}
__device__ __forceinline__ unsigned long long pack2(float x, float y) {
    unsigned long long r; asm("mov.b64 %0, {%1, %2};" : "=l"(r) : "f"(x), "f"(y)); return r;
}
__device__ __forceinline__ void unpack2(unsigned long long v, float& x, float& y) {
    asm("mov.b64 {%0, %1}, %2;" : "=f"(x), "=f"(y) : "l"(v));
}
__device__ __forceinline__ unsigned long long ffma2(unsigned long long a, unsigned long long b, unsigned long long c) {
    unsigned long long d; asm("fma.rn.f32x2 %0, %1, %2, %3;" : "=l"(d) : "l"(a), "l"(b), "l"(c)); return d;
}
__device__ __forceinline__ unsigned long long fadd2(unsigned long long a, unsigned long long b) {
    unsigned long long d; asm("add.rn.f32x2 %0, %1, %2;" : "=l"(d) : "l"(a), "l"(b)); return d;
}

// ---------------- content + width sniff (one warp) ----------------
__global__ void __launch_bounds__(32) crf_sniff_kernel(const unsigned int* __restrict__ a,
                                                       const unsigned int* __restrict__ b) {
    const int l = threadIdx.x;
    const unsigned int a0 = a[l], a1 = a[l + 32];
    const int am = __all_sync(0xffffffffu, ((a0 | a1) & 0xFEFEFEFEu) == 0u);
    const unsigned int* mp = am ? a : b;
    const unsigned int* tp = am ? b : a;
    const unsigned int m0 = mp[l], m1 = mp[l + 32];
    const int m8 = __any_sync(0xffffffffu, (m0 > 1u) || (m1 > 1u));
    const unsigned int todd = tp[2 * l + 1];
    const int t64 = __all_sync(0xffffffffu, todd == 0u);
    if (l == 0) {
        g_mask_ptr = (unsigned long long)mp;
        g_tags_ptr = (unsigned long long)tp;
        g_mask8 = m8;
        g_tags64 = t64;
    }
}

// ---------------- repack mask/tags ----------------
__global__ void crf_repack_kernel() {
    const int i = blockIdx.x * blockDim.x + threadIdx.x;
    if (i >= NSB) return;
    if (g_mask8) g_maskb[i] = (((const unsigned char*)g_mask_ptr)[i] != 0) ? 1 : 0;
    else         g_maskb[i] = (((const unsigned int*)g_mask_ptr)[i] != 0u) ? 1 : 0;
    if (g_tags64) g_tagsi[i] = (int)((const long long*)g_tags_ptr)[i];
    else          g_tagsi[i] = ((const int*)g_tags_ptr)[i];
}

// ---------------- prep ----------------
__global__ void crf_prep_kernel(const float* __restrict__ trans, const float* __restrict__ endt) {
    int i = blockIdx.x * blockDim.x + threadIdx.x;
    if (i < NT * NT) g_expT[i] = expf(trans[i]);
    if (i < NT)      g_expEnd[i] = expf(endt[i]);
}

// ---------------- forward: CTA = 128 threads = 1 batch, 4-way i-split ----------------
// Phase A (all lanes): warp w accumulates i-slice [16w,16w+16) for outputs j0=2l, j1=2l+1
//   (E slice register-resident: 32 regs), writes partials to sp[w].
// Phase B (lanes 0-7): reduce 4 partials for output pair jj=16w+2l, apply
//   g = exp2(em*L2E - 6) (prefetched 2 ahead) and the DELAYED renorm s2 from the
//   slot (published last step from v[0]'s exponent — delay-1 absolute renorm, stable,
//   bookkeeping exact: c += 6 + k each applied step).
#define CRF_STEP(T, G, QM, RB, WB, PB) do {                                      \
    /* phase A: slice matvec */                                                  \
    const ulonglong2* pv = (const ulonglong2*)(sv[RB] + i0);                     \
    unsigned long long a0 = 0ull, a1 = 0ull, b0 = 0ull, b1 = 0ull;               \
    _Pragma("unroll")                                                            \
    for (int q = 0; q < 4; ++q) {                                                \
        const ulonglong2 qq = pv[q];                                             \
        a0 = ffma2(qq.x, EA[2 * q],     a0);                                     \
        a1 = ffma2(qq.y, EA[2 * q + 1], a1);                                     \
        b0 = ffma2(qq.x, EB[2 * q],     b0);                                     \
        b1 = ffma2(qq.y, EB[2 * q + 1], b1);                                     \
    }                                                                            \
    float ax, ay, bx, by;                                                        \
    unpack2(fadd2(a0, a1), ax, ay);                                              \
    unpack2(fadd2(b0, b1), bx, by);                                              \
    *(float2*)&sp[w][j0] = make_float2(ax + ay, bx + by);                        \
    __syncthreads();                                                             \
    /* phase B: reduce + scale (lanes 0-7) */                                    \
    if (l < 8) {                                                                 \
        const unsigned long long P0 = *(const unsigned long long*)&sp[0][jj];    \
        const unsigned long long P1 = *(const unsigned long long*)&sp[1][jj];    \
        const unsigned long long P2 = *(const unsigned long long*)&sp[2][jj];    \
        const unsigned long long P3 = *(const unsigned long long*)&sp[3][jj];    \
        const unsigned long long ss = fadd2(fadd2(P0, P1), fadd2(P2, P3));       \
        float ox, oy; unpack2(ss, ox, oy);                                       \
        const float2 sk = *(const float2*)&slot[PB][0];                          \
        const int mcur = (QM);                                                   \
        const float2 gc = (G);                                                   \
        if (mcur) {                                                              \
            vx = ox * gc.x * sk.x;                                               \
            vy = oy * gc.y * sk.x;                                               \
            cacc += 6.0f + sk.y;                                                 \
        }                                                                        \
        { /* prefetch step T+2 */                                                \
            const int tp = (T) + 2;                                              \
            if (tp < SEQ) {                                                      \
                const float2 ep = *(const float2*)(emb + tp * NT + jj);          \
                G = make_float2(ex2f(fmaf(ep.x, L2E, -6.0f)),                    \
                                ex2f(fmaf(ep.y, L2E, -6.0f)));                   \
                QM = (int)mrow[tp];                                              \
            }                                                                    \
        }                                                                        \
        *(float2*)&sv[WB][jj] = make_float2(vx, vy);                             \
        if (w == 0 && l == 0) {                                                  \
            float s2n, kn;                                                       \
            if (mcur) {                                                          \
                const int eb = (__float_as_int(vx) >> 23) & 255;                 \
                kn = (float)(eb - 127);                                          \
                s2n = __int_as_float((254 - eb) << 23);                          \
            } else { s2n = sk.x; kn = sk.y; }                                    \
            *(float2*)&slot[(PB) ^ 1][0] = make_float2(s2n, kn);                 \
        }                                                                        \
    }                                                                            \
    __syncthreads();                                                             \
} while (0)

__global__ void __launch_bounds__(128, 4) crf_forward_kernel(
    const float* __restrict__ em, const float* __restrict__ startt)
{
    __shared__ __align__(16) float sv[2][NT];   // v double buffer
    __shared__ __align__(16) float sp[4][NT];   // per-warp partial slabs
    __shared__ __align__(8)  float slot[2][2];  // (s2, k) double-buffered renorm slot
    const int w = threadIdx.x >> 5;
    const int l = threadIdx.x & 31;
    const int b = blockIdx.x;
    const int j0 = 2 * l;
    const int i0 = SLICE * w;
    const int jj = i0 + 2 * (l & 7);
    const float L2E = 1.4426950408889634f;
    const float LN2 = 0.69314718055994531f;

    // E slice registers: EA[p]=(E[i0+2p][j0], E[i0+2p+1][j0]), EB same for j0+1
    unsigned long long EA[8], EB[8];
#pragma unroll
    for (int p = 0; p < 8; ++p) {
        EA[p] = pack2(g_expT[(i0 + 2 * p) * NT + j0],     g_expT[(i0 + 2 * p + 1) * NT + j0]);
        EB[p] = pack2(g_expT[(i0 + 2 * p) * NT + j0 + 1], g_expT[(i0 + 2 * p + 1) * NT + j0 + 1]);
    }

    const float* emb = em + (size_t)b * SEQ * NT;
    const unsigned char* mrow = g_maskb + (size_t)b * SEQ;

    float vx = 0.f, vy = 0.f, cacc = 0.f;
    float2 g0 = make_float2(0.f, 0.f), g1 = make_float2(0.f, 0.f);
    int qm0 = 0, qm1 = 0;

    if (l < 8) {
        const float2 st = *(const float2*)(startt + jj);
        const float2 e0 = *(const float2*)(emb + jj);
        vx = ex2f((st.x + e0.x) * L2E);
        vy = ex2f((st.y + e0.y) * L2E);
        *(float2*)&sv[0][jj] = make_float2(vx, vy);
        // prefetch steps 1, 2
        const float2 p1 = *(const float2*)(emb + 1 * NT + jj);
        g0 = make_float2(ex2f(fmaf(p1.x, L2E, -6.0f)), ex2f(fmaf(p1.y, L2E, -6.0f)));
        qm0 = (int)mrow[1];
        const float2 p2 = *(const float2*)(emb + 2 * NT + jj);
        g1 = make_float2(ex2f(fmaf(p2.x, L2E, -6.0f)), ex2f(fmaf(p2.y, L2E, -6.0f)));
        qm1 = (int)mrow[2];
    }
    if (w == 0 && l == 0) { slot[1][0] = 1.0f; slot[1][1] = 0.0f; }
    __syncthreads();

    // steps 1..1022 in parity pairs, then 1023
    for (int t = 1; t <= SEQ - 3; t += 2) {
        CRF_STEP(t,     g0, qm0, 0, 1, 1);
        CRF_STEP(t + 1, g1, qm1, 1, 0, 0);
    }
    CRF_STEP(SEQ - 1, g0, qm0, 0, 1, 1);

    // finalize: logz = (lg2(sum_j v_j*expEnd_j) + c) * ln2
    if (l < 8) {
        float s = vx * g_expEnd[jj] + vy * g_expEnd[jj + 1];
#pragma unroll
        for (int off = 4; off > 0; off >>= 1)
            s += __shfl_xor_sync(0x000000ffu, s, off, 8);
        if (l == 0) sp[0][w] = s;
    }
    __syncthreads();
    if (w == 0 && l == 0) {
        const float s = sp[0][0] + sp[0][1] + sp[0][2] + sp[0][3];
        g_logz[b] = (lg2f(s) + cacc) * LN2;
    }
}

// ---------------- gold-path score ----------------
__global__ void __launch_bounds__(256) crf_score_kernel(
    const float* __restrict__ em, const float* __restrict__ startt,
    const float* __restrict__ endt, const float* __restrict__ trans)
{
    const int warp = threadIdx.x >> 5;
    const int lane = threadIdx.x & 31;
    const int b = blockIdx.x * 8 + warp;
    if (b >= BATCH) return;
    const float* emb = em + (size_t)b * SEQ * NT;
    const unsigned char* mrow = g_maskb + (size_t)b * SEQ;
    const int* tg = g_tagsi + (size_t)b * SEQ;

    float acc = 0.f;
    int msum = 0;
    for (int s = lane; s < SEQ; s += 32) {
        const int tcur = tg[s];
        const int mk = (int)mrow[s];
        const float e = emb[s * NT + tcur];
        float contrib;
        if (s == 0) contrib = e + startt[tcur];
        else {
            const int tprev = tg[s - 1];
            contrib = mk ? (e + trans[tprev * NT + tcur]) : 0.f;
        }
        acc += contrib;
        msum += mk ? 1 : 0;
    }
#pragma unroll
    for (int off = 16; off > 0; off >>= 1) {
        acc  += __shfl_xor_sync(0xffffffffu, acc, off);
        msum += __shfl_xor_sync(0xffffffffu, msum, off);
    }
    if (lane == 0) {
        const int send = msum - 1;
        g_score[b] = acc + endt[tg[send]];
    }
}

// ---------------- final reduce ----------------
__global__ void crf_reduce_kernel(float* __restrict__ out) {
    __shared__ float sh[BATCH];
    const int i = threadIdx.x;
    sh[i] = g_logz[i] - g_score[i];
    __syncthreads();
#pragma unroll
    for (int off = BATCH / 2; off > 0; off >>= 1) {
        if (i < off) sh[i] += sh[i + off];
        __syncthreads();
    }
    if (i == 0) out[0] = sh[0];
}

// ---------------- launch ----------------
extern "C" void kernel_launch(void* const* d_in, const int* in_sizes, int n_in,
                              void* d_out, int out_size) {
    int i_em = 0;
    for (int i = 1; i < n_in; ++i) if (in_sizes[i] > in_sizes[i_em]) i_em = i;

    int i_tr = -1, i_s1 = -1, i_s2 = -1, i_b1 = -1, i_b2 = -1;
    for (int i = 0; i < n_in; ++i) {
        if (i == i_em) continue;
        if (in_sizes[i] == NT * NT) { i_tr = i; }
        else if (in_sizes[i] == NT) { if (i_s1 < 0) i_s1 = i; else i_s2 = i; }
        else { if (i_b1 < 0) i_b1 = i; else i_b2 = i; }
    }

    const float* em     = (const float*)d_in[i_em];
    const float* trans  = (const float*)d_in[i_tr];
    const float* startt = (const float*)d_in[i_s1];
    const float* endt   = (const float*)d_in[i_s2];

    crf_sniff_kernel<<<1, 32>>>((const unsigned int*)d_in[i_b1],
                                (const unsigned int*)d_in[i_b2]);
    crf_repack_kernel<<<NSB / 256, 256>>>();
    crf_prep_kernel<<<(NT * NT + 255) / 256, 256>>>(trans, endt);
    crf_forward_kernel<<<BATCH, 128>>>(em, startt);
    crf_score_kernel<<<BATCH / 8, 256>>>(em, startt, endt, trans);
    crf_reduce_kernel<<<1, BATCH>>>((float*)d_out);
}

// round 8
// speedup vs baseline: 1.8485x; 1.8485x over previous
#include <cuda_runtime.h>
#include <cuda_bf16.h>
#include <cstdint>

#define BATCH 512
#define SEQ   1024
#define NT    64
#define NSB   (BATCH * SEQ)
#define FW_WARPS 4

// ---------------- device scratch (no allocs allowed) ----------------
__device__ float g_expT[NT * NT];   // exp(transitions)
__device__ float g_expEnd[NT];      // exp(end_transitions)
__device__ float g_logz[BATCH];
__device__ float g_score[BATCH];
__device__ unsigned long long g_mask_ptr;   // resolved raw mask pointer
__device__ unsigned long long g_tags_ptr;   // resolved raw tags pointer
__device__ int   g_mask8;                   // 1 if mask is 1 byte/elem, 0 if int32
__device__ int   g_tags64;                  // 1 if tags are int64, 0 if int32
__device__ unsigned char g_maskb[NSB];      // canonical mask (1 byte/elem)
__device__ int           g_tagsi[NSB];      // canonical tags (int32)

// ---------------- small PTX helpers ----------------
__device__ __forceinline__ float ex2f(float x) {
    float r; asm("ex2.approx.ftz.f32 %0, %1;" : "=f"(r) : "f"(x)); return r;
}
__device__ __forceinline__ float lg2f(float x) {
    float r; asm("lg2.approx.ftz.f32 %0, %1;" : "=f"(r) : "f"(x)); return r;
}
__device__ __forceinline__ unsigned long long pack2(float x, float y) {
    unsigned long long r; asm("mov.b64 %0, {%1, %2};" : "=l"(r) : "f"(x), "f"(y)); return r;
}
__device__ __forceinline__ void unpack2(unsigned long long v, float& x, float& y) {
    asm("mov.b64 {%0, %1}, %2;" : "=f"(x), "=f"(y) : "l"(v));
}
__device__ __forceinline__ unsigned long long ffma2(unsigned long long a, unsigned long long b, unsigned long long c) {
    unsigned long long d; asm("fma.rn.f32x2 %0, %1, %2, %3;" : "=l"(d) : "l"(a), "l"(b), "l"(c)); return d;
}
__device__ __forceinline__ unsigned long long fadd2(unsigned long long a, unsigned long long b) {
    unsigned long long d; asm("add.rn.f32x2 %0, %1, %2;" : "=l"(d) : "l"(a), "l"(b)); return d;
}

// ---------------- content + width sniff (one warp, parallel) ----------------
__global__ void __launch_bounds__(32) crf_sniff_kernel(const unsigned int* __restrict__ a,
                                                       const unsigned int* __restrict__ b) {
    const int l = threadIdx.x;
    const unsigned int a0 = a[l], a1 = a[l + 32];
    const int am = __all_sync(0xffffffffu, ((a0 | a1) & 0xFEFEFEFEu) == 0u);
    const unsigned int* mp = am ? a : b;
    const unsigned int* tp = am ? b : a;
    const unsigned int m0 = mp[l], m1 = mp[l + 32];
    const int m8 = __any_sync(0xffffffffu, (m0 > 1u) || (m1 > 1u));
    const unsigned int todd = tp[2 * l + 1];
    const int t64 = __all_sync(0xffffffffu, todd == 0u);
    if (l == 0) {
        g_mask_ptr = (unsigned long long)mp;
        g_tags_ptr = (unsigned long long)tp;
        g_mask8 = m8;
        g_tags64 = t64;
    }
}

// ---------------- repack mask/tags into canonical layouts ----------------
__global__ void crf_repack_kernel() {
    const int i = blockIdx.x * blockDim.x + threadIdx.x;
    if (i >= NSB) return;
    if (g_mask8) g_maskb[i] = (((const unsigned char*)g_mask_ptr)[i] != 0) ? 1 : 0;
    else         g_maskb[i] = (((const unsigned int*)g_mask_ptr)[i] != 0u) ? 1 : 0;
    if (g_tags64) g_tagsi[i] = (int)((const long long*)g_tags_ptr)[i];
    else          g_tagsi[i] = ((const int*)g_tags_ptr)[i];
}

// ---------------- prep: E = exp(T), expEnd = exp(end) ----------------
__global__ void crf_prep_kernel(const float* __restrict__ trans, const float* __restrict__ endt) {
    int i = blockIdx.x * blockDim.x + threadIdx.x;
    if (i < NT * NT) g_expT[i] = expf(trans[i]);
    if (i < NT)      g_expEnd[i] = expf(endt[i]);
}

// ---------------- forward: 4 warps/CTA, one batch per warp ----------------
// Lane l owns adjacent outputs j0=2l, j1=2l+1.
// v stored as float2(v_{2l}, v_{2l+1}); read back as 16 broadcast LDS.128.
// 8 accumulator chains of depth 8 (was 4x16) -> serial FFMA chain 32 cyc.
// NO __syncwarp between STS and next LDS: warp is fully convergent, same-warp
// shared-memory ops retire through the LSU in issue order (warp-synchronous
// smem communication). If this were unsafe the result would be garbage and
// the harness would catch it.
// Invariant: alpha[j] = ln(v[j]) + c*ln2.
// Step: out_j = sum_i v_i E_ij; v' = out * g, g = exp2(em*L2E - 6) (prefetched); c += 6.
// Every 8th step: absolute renorm by 2^(133-eb(out_{j=0})); c += eb - 127 (exact).
#define CRF_STEP(T, G, QM, RBUF, WBUF, REN) do {                                 \
    const int    mcur = (QM);                                                    \
    const float2 gc   = (G);                                                     \
    { /* prefetch step T+4 */                                                    \
        const int tp = (T) + 4;                                                  \
        if (tp < SEQ) {                                                          \
            const float2 e2 = *(const float2*)(emb + tp * NT + j0);              \
            G = make_float2(ex2f(fmaf(e2.x, L2E, -6.0f)),                        \
                            ex2f(fmaf(e2.y, L2E, -6.0f)));                       \
            QM = (int)mrow[tp];                                                  \
        }                                                                        \
    }                                                                            \
    const ulonglong2* pb = (const ulonglong2*)(pd[wid][RBUF]);                   \
    unsigned long long a0 = 0ull, a1 = 0ull, a2 = 0ull, a3 = 0ull;               \
    unsigned long long b0 = 0ull, b1 = 0ull, b2 = 0ull, b3 = 0ull;               \
    _Pragma("unroll")                                                            \
    for (int q = 0; q < 8; ++q) {                                                \
        const ulonglong2 q0 = pb[2 * q];                                         \
        const ulonglong2 q1 = pb[2 * q + 1];                                     \
        a0 = ffma2(q0.x, EA[4 * q],     a0);                                     \
        a1 = ffma2(q0.y, EA[4 * q + 1], a1);                                     \
        a2 = ffma2(q1.x, EA[4 * q + 2], a2);                                     \
        a3 = ffma2(q1.y, EA[4 * q + 3], a3);                                     \
        b0 = ffma2(q0.x, EB[4 * q],     b0);                                     \
        b1 = ffma2(q0.y, EB[4 * q + 1], b1);                                     \
        b2 = ffma2(q1.x, EB[4 * q + 2], b2);                                     \
        b3 = ffma2(q1.y, EB[4 * q + 3], b3);                                     \
    }                                                                            \
    const unsigned long long ta = fadd2(fadd2(a0, a1), fadd2(a2, a3));           \
    const unsigned long long tb = fadd2(fadd2(b0, b1), fadd2(b2, b3));           \
    float ax, ay, bx, by;                                                        \
    unpack2(ta, ax, ay); unpack2(tb, bx, by);                                    \
    const float outA = ax + ay;                                                  \
    const float outB = bx + by;                                                  \
    if (REN) {                                                                   \
        const float arefn = __shfl_sync(0xffffffffu, outA, 0);                   \
        const int eb = (__float_as_int(arefn) >> 23) & 255;                      \
        if (mcur) {                                                              \
            const float s2 = __int_as_float((260 - eb) << 23);                   \
            vx = outA * gc.x * s2;                                               \
            vy = outB * gc.y * s2;                                               \
            c += eb - 127;                                                       \
        }                                                                        \
    } else if (mcur) {                                                           \
        vx = outA * gc.x;                                                        \
        vy = outB * gc.y;                                                        \
        c += 6;                                                                  \
    }                                                                            \
    ((float2*)pd[wid][WBUF])[l] = make_float2(vx, vy);                           \
} while (0)

__global__ void __launch_bounds__(32 * FW_WARPS, 1) crf_forward_kernel(
    const float* __restrict__ em, const float* __restrict__ startt)
{
    __shared__ __align__(16) float pd[FW_WARPS][2][NT];  // per-warp double buffer
    const int wid = threadIdx.x >> 5;
    const int l = threadIdx.x & 31;
    const int b = blockIdx.x * FW_WARPS + wid;
    const int j0 = 2 * l;
    const float L2E = 1.4426950408889634f;
    const float LN2 = 0.69314718055994531f;

    // register-resident E column pairs: EA[p]=(E[2p][j0], E[2p+1][j0]), EB for j0+1
    unsigned long long EA[32], EB[32];
#pragma unroll
    for (int p = 0; p < 32; ++p) {
        EA[p] = pack2(g_expT[(2 * p) * NT + j0],     g_expT[(2 * p + 1) * NT + j0]);
        EB[p] = pack2(g_expT[(2 * p) * NT + j0 + 1], g_expT[(2 * p + 1) * NT + j0 + 1]);
    }

    const float* emb = em + (size_t)b * SEQ * NT;
    const unsigned char* mrow = g_maskb + (size_t)b * SEQ;

    // init: v0 = exp(start + em0)
    const float2 st2 = *(const float2*)(startt + j0);
    const float2 e02 = *(const float2*)(emb + j0);
    float vx = ex2f((st2.x + e02.x) * L2E);
    float vy = ex2f((st2.y + e02.y) * L2E);
    int c = 0;

    ((float2*)pd[wid][0])[l] = make_float2(vx, vy);

    // prefetch slots for steps 1..4 (slot = (step-1) & 3)
    float2 g0, g1, g2, g3;
    int qm0, qm1, qm2, qm3;
    {
        const float2 p1 = *(const float2*)(emb + 1 * NT + j0);
        g0 = make_float2(ex2f(fmaf(p1.x, L2E, -6.0f)), ex2f(fmaf(p1.y, L2E, -6.0f)));
        qm0 = (int)mrow[1];
        const float2 p2 = *(const float2*)(emb + 2 * NT + j0);
        g1 = make_float2(ex2f(fmaf(p2.x, L2E, -6.0f)), ex2f(fmaf(p2.y, L2E, -6.0f)));
        qm1 = (int)mrow[2];
        const float2 p3 = *(const float2*)(emb + 3 * NT + j0);
        g2 = make_float2(ex2f(fmaf(p3.x, L2E, -6.0f)), ex2f(fmaf(p3.y, L2E, -6.0f)));
        qm2 = (int)mrow[3];
        const float2 p4 = *(const float2*)(emb + 4 * NT + j0);
        g3 = make_float2(ex2f(fmaf(p4.x, L2E, -6.0f)), ex2f(fmaf(p4.y, L2E, -6.0f)));
        qm3 = (int)mrow[4];
    }

    // main loop: steps 1..1016, unroll 8; renorm every 8th
    for (int t = 1; t <= SEQ - 15; t += 8) {
        CRF_STEP(t + 0, g0, qm0, 0, 1, false);
        CRF_STEP(t + 1, g1, qm1, 1, 0, false);
        CRF_STEP(t + 2, g2, qm2, 0, 1, false);
        CRF_STEP(t + 3, g3, qm3, 1, 0, false);
        CRF_STEP(t + 4, g0, qm0, 0, 1, false);
        CRF_STEP(t + 5, g1, qm1, 1, 0, false);
        CRF_STEP(t + 6, g2, qm2, 0, 1, false);
        CRF_STEP(t + 7, g3, qm3, 1, 0, true);
    }
    // tail: steps 1017..1023
    CRF_STEP(SEQ - 7, g0, qm0, 0, 1, false);
    CRF_STEP(SEQ - 6, g1, qm1, 1, 0, false);
    CRF_STEP(SEQ - 5, g2, qm2, 0, 1, false);
    CRF_STEP(SEQ - 4, g3, qm3, 1, 0, false);
    CRF_STEP(SEQ - 3, g0, qm0, 0, 1, false);
    CRF_STEP(SEQ - 2, g1, qm1, 1, 0, false);
    CRF_STEP(SEQ - 1, g2, qm2, 0, 1, false);

    // finalize: log_z = ln(sum_j v_j * expEnd_j) + c*ln2
    float s = vx * g_expEnd[j0] + vy * g_expEnd[j0 + 1];
#pragma unroll
    for (int off = 16; off > 0; off >>= 1)
        s += __shfl_xor_sync(0xffffffffu, s, off);
    if (l == 0) g_logz[b] = (lg2f(s) + (float)c) * LN2;
}

// ---------------- gold-path score: one warp per batch ----------------
__global__ void __launch_bounds__(256) crf_score_kernel(
    const float* __restrict__ em, const float* __restrict__ startt,
    const float* __restrict__ endt, const float* __restrict__ trans)
{
    const int warp = threadIdx.x >> 5;
    const int lane = threadIdx.x & 31;
    const int b = blockIdx.x * 8 + warp;
    if (b >= BATCH) return;
    const float* emb = em + (size_t)b * SEQ * NT;
    const unsigned char* mrow = g_maskb + (size_t)b * SEQ;
    const int* tg = g_tagsi + (size_t)b * SEQ;

    float acc = 0.f;
    int msum = 0;
    for (int s = lane; s < SEQ; s += 32) {
        const int tcur = tg[s];
        const int mk = (int)mrow[s];
        const float e = emb[s * NT + tcur];
        float contrib;
        if (s == 0) contrib = e + startt[tcur];
        else {
            const int tprev = tg[s - 1];
            contrib = mk ? (e + trans[tprev * NT + tcur]) : 0.f;
        }
        acc += contrib;
        msum += mk ? 1 : 0;
    }
#pragma unroll
    for (int off = 16; off > 0; off >>= 1) {
        acc  += __shfl_xor_sync(0xffffffffu, acc, off);
        msum += __shfl_xor_sync(0xffffffffu, msum, off);
    }
    if (lane == 0) {
        const int send = msum - 1;
        g_score[b] = acc + endt[tg[send]];
    }
}

// ---------------- final deterministic reduce ----------------
__global__ void crf_reduce_kernel(float* __restrict__ out) {
    __shared__ float sh[BATCH];
    const int i = threadIdx.x;
    sh[i] = g_logz[i] - g_score[i];
    __syncthreads();
#pragma unroll
    for (int off = BATCH / 2; off > 0; off >>= 1) {
        if (i < off) sh[i] += sh[i + off];
        __syncthreads();
    }
    if (i == 0) out[0] = sh[0];
}

// ---------------- launch: size-based dispatch + content sniff ----------------
extern "C" void kernel_launch(void* const* d_in, const int* in_sizes, int n_in,
                              void* d_out, int out_size) {
    int i_em = 0;
    for (int i = 1; i < n_in; ++i) if (in_sizes[i] > in_sizes[i_em]) i_em = i;

    int i_tr = -1, i_s1 = -1, i_s2 = -1, i_b1 = -1, i_b2 = -1;
    for (int i = 0; i < n_in; ++i) {
        if (i == i_em) continue;
        if (in_sizes[i] == NT * NT) { i_tr = i; }
        else if (in_sizes[i] == NT) { if (i_s1 < 0) i_s1 = i; else i_s2 = i; }
        else { if (i_b1 < 0) i_b1 = i; else i_b2 = i; }
    }

    const float* em     = (const float*)d_in[i_em];
    const float* trans  = (const float*)d_in[i_tr];
    const float* startt = (const float*)d_in[i_s1];
    const float* endt   = (const float*)d_in[i_s2];

    crf_sniff_kernel<<<1, 32>>>((const unsigned int*)d_in[i_b1],
                                (const unsigned int*)d_in[i_b2]);
    crf_repack_kernel<<<NSB / 256, 256>>>();
    crf_prep_kernel<<<(NT * NT + 255) / 256, 256>>>(trans, endt);
    crf_forward_kernel<<<BATCH / FW_WARPS, 32 * FW_WARPS>>>(em, startt);
    crf_score_kernel<<<BATCH / 8, 256>>>(em, startt, endt, trans);
    crf_reduce_kernel<<<1, BATCH>>>((float*)d_out);
}

// round 10
// speedup vs baseline: 2.5193x; 1.3628x over previous
#include <cuda_runtime.h>
#include <cuda_bf16.h>
#include <cstdint>

#define BATCH 512
#define SEQ   1024
#define NT    64
#define NSB   (BATCH * SEQ)
#define FW_WARPS 4

// ---------------- device scratch (no allocs allowed) ----------------
__device__ float g_expT[NT * NT];   // exp(transitions)
__device__ float g_expEnd[NT];      // exp(end_transitions)
__device__ float g_logz[BATCH];
__device__ float g_score[BATCH];
__device__ unsigned long long g_mask_ptr;
__device__ unsigned long long g_tags_ptr;
__device__ int   g_mask8;
__device__ int   g_tags64;
__device__ unsigned char g_maskb[NSB];
__device__ int           g_tagsi[NSB];

// ---------------- small PTX helpers ----------------
__device__ __forceinline__ float ex2f(float x) {
    float r; asm("ex2.approx.ftz.f32 %0, %1;" : "=f"(r) : "f"(x)); return r;
}
__device__ __forceinline__ float lg2f(float x) {
    float r; asm("lg2.approx.ftz.f32 %0, %1;" : "=f"(r) : "f"(x)); return r;
}
__device__ __forceinline__ unsigned long long pack2(float x, float y) {
    unsigned long long r; asm("mov.b64 %0, {%1, %2};" : "=l"(r) : "f"(x), "f"(y)); return r;
}
__device__ __forceinline__ void unpack2(unsigned long long v, float& x, float& y) {
    asm("mov.b64 {%0, %1}, %2;" : "=f"(x), "=f"(y) : "l"(v));
}
__device__ __forceinline__ unsigned long long ffma2(unsigned long long a, unsigned long long b, unsigned long long c) {
    unsigned long long d; asm("fma.rn.f32x2 %0, %1, %2, %3;" : "=l"(d) : "l"(a), "l"(b), "l"(c)); return d;
}
__device__ __forceinline__ unsigned long long fadd2(unsigned long long a, unsigned long long b) {
    unsigned long long d; asm("add.rn.f32x2 %0, %1, %2;" : "=l"(d) : "l"(a), "l"(b)); return d;
}

// ---------------- content + width sniff (one warp, parallel) ----------------
__global__ void __launch_bounds__(32) crf_sniff_kernel(const unsigned int* __restrict__ a,
                                                       const unsigned int* __restrict__ b) {
    const int l = threadIdx.x;
    const unsigned int a0 = a[l], a1 = a[l + 32];
    const int am = __all_sync(0xffffffffu, ((a0 | a1) & 0xFEFEFEFEu) == 0u);
    const unsigned int* mp = am ? a : b;
    const unsigned int* tp = am ? b : a;
    const unsigned int m0 = mp[l], m1 = mp[l + 32];
    const int m8 = __any_sync(0xffffffffu, (m0 > 1u) || (m1 > 1u));
    const unsigned int todd = tp[2 * l + 1];
    const int t64 = __all_sync(0xffffffffu, todd == 0u);
    if (l == 0) {
        g_mask_ptr = (unsigned long long)mp;
        g_tags_ptr = (unsigned long long)tp;
        g_mask8 = m8;
        g_tags64 = t64;
    }
}

// ---------------- repack mask/tags into canonical layouts ----------------
__global__ void crf_repack_kernel() {
    const int i = blockIdx.x * blockDim.x + threadIdx.x;
    if (i >= NSB) return;
    if (g_mask8) g_maskb[i] = (((const unsigned char*)g_mask_ptr)[i] != 0) ? 1 : 0;
    else         g_maskb[i] = (((const unsigned int*)g_mask_ptr)[i] != 0u) ? 1 : 0;
    if (g_tags64) g_tagsi[i] = (int)((const long long*)g_tags_ptr)[i];
    else          g_tagsi[i] = ((const int*)g_tags_ptr)[i];
}

// ---------------- prep: E = exp(T), expEnd = exp(end) ----------------
__global__ void crf_prep_kernel(const float* __restrict__ trans, const float* __restrict__ endt) {
    int i = blockIdx.x * blockDim.x + threadIdx.x;
    if (i < NT * NT) g_expT[i] = expf(trans[i]);
    if (i < NT)      g_expEnd[i] = expf(endt[i]);
}

// ---------------- forward: 4 warps/CTA, one batch per warp ----------------
// Lane l owns adjacent outputs j0=2l, j1=2l+1.
// THREE-STAGE emission pipeline (kills the per-step exposed LDG->MUFU stall):
//   step T:  uses G (ex2-converted at T-4 from data loaded at T-8),
//            converts G = ex2(raw)   [raw loaded at T-4, >1000cyc ago],
//            loads raw = emb[T+8].
// Mask QM: loaded at T-4, used at T (covered).
// Invariant: alpha[j] = ln(v[j]) + c*ln2.
// Step: out_j = sum_i v_i E_ij; v' = out * g; c += 6.  Renorm every 8th step
// by 2^(133-eb(out_0)); c += eb - 127 (exact power-of-2 bookkeeping).
#define CRF_STEP(T, G, R, QM, RBUF, WBUF, REN) do {                              \
    const int    mcur = (QM);                                                    \
    const float2 gc   = (G);                                                     \
    /* convert for step T+4 (raw loaded at T-4) */                               \
    (G) = make_float2(ex2f(fmaf((R).x, L2E, -6.0f)),                             \
                      ex2f(fmaf((R).y, L2E, -6.0f)));                            \
    /* load for step T+8 */                                                      \
    { const int tl = (T) + 8; if (tl < SEQ)                                      \
        (R) = *(const float2*)(emb + tl * NT + j0); }                            \
    /* mask for step T+4 */                                                      \
    { const int tm = (T) + 4; if (tm < SEQ) (QM) = (int)mrow[tm]; }              \
    const ulonglong2* pb = (const ulonglong2*)(pd[wid][RBUF]);                   \
    unsigned long long a0 = 0ull, a1 = 0ull, a2 = 0ull, a3 = 0ull;               \
    unsigned long long b0 = 0ull, b1 = 0ull, b2 = 0ull, b3 = 0ull;               \
    _Pragma("unroll")                                                            \
    for (int q = 0; q < 8; ++q) {                                                \
        const ulonglong2 q0 = pb[2 * q];                                         \
        const ulonglong2 q1 = pb[2 * q + 1];                                     \
        a0 = ffma2(q0.x, EA[4 * q],     a0);                                     \
        a1 = ffma2(q0.y, EA[4 * q + 1], a1);                                     \
        a2 = ffma2(q1.x, EA[4 * q + 2], a2);                                     \
        a3 = ffma2(q1.y, EA[4 * q + 3], a3);                                     \
        b0 = ffma2(q0.x, EB[4 * q],     b0);                                     \
        b1 = ffma2(q0.y, EB[4 * q + 1], b1);                                     \
        b2 = ffma2(q1.x, EB[4 * q + 2], b2);                                     \
        b3 = ffma2(q1.y, EB[4 * q + 3], b3);                                     \
    }                                                                            \
    const unsigned long long ta = fadd2(fadd2(a0, a1), fadd2(a2, a3));           \
    const unsigned long long tb = fadd2(fadd2(b0, b1), fadd2(b2, b3));           \
    float ax, ay, bx, by;                                                        \
    unpack2(ta, ax, ay); unpack2(tb, bx, by);                                    \
    const float outA = ax + ay;                                                  \
    const float outB = bx + by;                                                  \
    if (REN) {                                                                   \
        const float arefn = __shfl_sync(0xffffffffu, outA, 0);                   \
        const int eb = (__float_as_int(arefn) >> 23) & 255;                      \
        if (mcur) {                                                              \
            const float s2 = __int_as_float((260 - eb) << 23);                   \
            vx = outA * gc.x * s2;                                               \
            vy = outB * gc.y * s2;                                               \
            c += eb - 127;                                                       \
        }                                                                        \
    } else if (mcur) {                                                           \
        vx = outA * gc.x;                                                        \
        vy = outB * gc.y;                                                        \
        c += 6;                                                                  \
    }                                                                            \
    ((float2*)pd[wid][WBUF])[l] = make_float2(vx, vy);                           \
} while (0)

__global__ void __launch_bounds__(32 * FW_WARPS, 1) crf_forward_kernel(
    const float* __restrict__ em, const float* __restrict__ startt)
{
    __shared__ __align__(16) float pd[FW_WARPS][2][NT];  // per-warp double buffer
    const int wid = threadIdx.x >> 5;
    const int l = threadIdx.x & 31;
    const int b = blockIdx.x * FW_WARPS + wid;
    const int j0 = 2 * l;
    const float L2E = 1.4426950408889634f;
    const float LN2 = 0.69314718055994531f;

    // register-resident E column pairs: EA[p]=(E[2p][j0], E[2p+1][j0]), EB for j0+1
    unsigned long long EA[32], EB[32];
#pragma unroll
    for (int p = 0; p < 32; ++p) {
        EA[p] = pack2(g_expT[(2 * p) * NT + j0],     g_expT[(2 * p + 1) * NT + j0]);
        EB[p] = pack2(g_expT[(2 * p) * NT + j0 + 1], g_expT[(2 * p + 1) * NT + j0 + 1]);
    }

    const float* emb = em + (size_t)b * SEQ * NT;
    const unsigned char* mrow = g_maskb + (size_t)b * SEQ;

    // init: v0 = exp(start + em0)
    const float2 st2 = *(const float2*)(startt + j0);
    const float2 e02 = *(const float2*)(emb + j0);
    float vx = ex2f((st2.x + e02.x) * L2E);
    float vy = ex2f((st2.y + e02.y) * L2E);
    int c = 0;

    ((float2*)pd[wid][0])[l] = make_float2(vx, vy);

    // pipeline prologue:
    //   G slots: converted emissions for steps 1..4
    //   R slots: raw emissions for steps 5..8
    //   QM slots: masks for steps 1..4
    float2 g0, g1, g2, g3, r0, r1, r2, r3;
    int qm0, qm1, qm2, qm3;
    {
        const float2 p1 = *(const float2*)(emb + 1 * NT + j0);
        const float2 p2 = *(const float2*)(emb + 2 * NT + j0);
        const float2 p3 = *(const float2*)(emb + 3 * NT + j0);
        const float2 p4 = *(const float2*)(emb + 4 * NT + j0);
        g0 = make_float2(ex2f(fmaf(p1.x, L2E, -6.0f)), ex2f(fmaf(p1.y, L2E, -6.0f)));
        g1 = make_float2(ex2f(fmaf(p2.x, L2E, -6.0f)), ex2f(fmaf(p2.y, L2E, -6.0f)));
        g2 = make_float2(ex2f(fmaf(p3.x, L2E, -6.0f)), ex2f(fmaf(p3.y, L2E, -6.0f)));
        g3 = make_float2(ex2f(fmaf(p4.x, L2E, -6.0f)), ex2f(fmaf(p4.y, L2E, -6.0f)));
        r0 = *(const float2*)(emb + 5 * NT + j0);
        r1 = *(const float2*)(emb + 6 * NT + j0);
        r2 = *(const float2*)(emb + 7 * NT + j0);
        r3 = *(const float2*)(emb + 8 * NT + j0);
        qm0 = (int)mrow[1];
        qm1 = (int)mrow[2];
        qm2 = (int)mrow[3];
        qm3 = (int)mrow[4];
    }

    // main loop: steps 1..1016, unroll 8; renorm every 8th
    for (int t = 1; t <= SEQ - 15; t += 8) {
        CRF_STEP(t + 0, g0, r0, qm0, 0, 1, false);
        CRF_STEP(t + 1, g1, r1, qm1, 1, 0, false);
        CRF_STEP(t + 2, g2, r2, qm2, 0, 1, false);
        CRF_STEP(t + 3, g3, r3, qm3, 1, 0, false);
        CRF_STEP(t + 4, g0, r0, qm0, 0, 1, false);
        CRF_STEP(t + 5, g1, r1, qm1, 1, 0, false);
        CRF_STEP(t + 6, g2, r2, qm2, 0, 1, false);
        CRF_STEP(t + 7, g3, r3, qm3, 1, 0, true);
    }
    // tail: steps 1017..1023 (guards in the macro handle OOB loads)
    CRF_STEP(SEQ - 7, g0, r0, qm0, 0, 1, false);
    CRF_STEP(SEQ - 6, g1, r1, qm1, 1, 0, false);
    CRF_STEP(SEQ - 5, g2, r2, qm2, 0, 1, false);
    CRF_STEP(SEQ - 4, g3, r3, qm3, 1, 0, false);
    CRF_STEP(SEQ - 3, g0, r0, qm0, 0, 1, false);
    CRF_STEP(SEQ - 2, g1, r1, qm1, 1, 0, false);
    CRF_STEP(SEQ - 1, g2, r2, qm2, 0, 1, false);

    // finalize: log_z = ln(sum_j v_j * expEnd_j) + c*ln2
    float s = vx * g_expEnd[j0] + vy * g_expEnd[j0 + 1];
#pragma unroll
    for (int off = 16; off > 0; off >>= 1)
        s += __shfl_xor_sync(0xffffffffu, s, off);
    if (l == 0) g_logz[b] = (lg2f(s) + (float)c) * LN2;
}

// ---------------- gold-path score: one warp per batch ----------------
__global__ void __launch_bounds__(256) crf_score_kernel(
    const float* __restrict__ em, const float* __restrict__ startt,
    const float* __restrict__ endt, const float* __restrict__ trans)
{
    const int warp = threadIdx.x >> 5;
    const int lane = threadIdx.x & 31;
    const int b = blockIdx.x * 8 + warp;
    if (b >= BATCH) return;
    const float* emb = em + (size_t)b * SEQ * NT;
    const unsigned char* mrow = g_maskb + (size_t)b * SEQ;
    const int* tg = g_tagsi + (size_t)b * SEQ;

    float acc = 0.f;
    int msum = 0;
    for (int s = lane; s < SEQ; s += 32) {
        const int tcur = tg[s];
        const int mk = (int)mrow[s];
        const float e = emb[s * NT + tcur];
        float contrib;
        if (s == 0) contrib = e + startt[tcur];
        else {
            const int tprev = tg[s - 1];
            contrib = mk ? (e + trans[tprev * NT + tcur]) : 0.f;
        }
        acc += contrib;
        msum += mk ? 1 : 0;
    }
#pragma unroll
    for (int off = 16; off > 0; off >>= 1) {
        acc  += __shfl_xor_sync(0xffffffffu, acc, off);
        msum += __shfl_xor_sync(0xffffffffu, msum, off);
    }
    if (lane == 0) {
        const int send = msum - 1;
        g_score[b] = acc + endt[tg[send]];
    }
}

// ---------------- final deterministic reduce ----------------
__global__ void crf_reduce_kernel(float* __restrict__ out) {
    __shared__ float sh[BATCH];
    const int i = threadIdx.x;
    sh[i] = g_logz[i] - g_score[i];
    __syncthreads();
#pragma unroll
    for (int off = BATCH / 2; off > 0; off >>= 1) {
        if (i < off) sh[i] += sh[i + off];
        __syncthreads();
    }
    if (i == 0) out[0] = sh[0];
}

// ---------------- launch: size-based dispatch + content sniff ----------------
extern "C" void kernel_launch(void* const* d_in, const int* in_sizes, int n_in,
                              void* d_out, int out_size) {
    int i_em = 0;
    for (int i = 1; i < n_in; ++i) if (in_sizes[i] > in_sizes[i_em]) i_em = i;

    int i_tr = -1, i_s1 = -1, i_s2 = -1, i_b1 = -1, i_b2 = -1;
    for (int i = 0; i < n_in; ++i) {
        if (i == i_em) continue;
        if (in_sizes[i] == NT * NT) { i_tr = i; }
        else if (in_sizes[i] == NT) { if (i_s1 < 0) i_s1 = i; else i_s2 = i; }
        else { if (i_b1 < 0) i_b1 = i; else i_b2 = i; }
    }

    const float* em     = (const float*)d_in[i_em];
    const float* trans  = (const float*)d_in[i_tr];
    const float* startt = (const float*)d_in[i_s1];
    const float* endt   = (const float*)d_in[i_s2];

    crf_sniff_kernel<<<1, 32>>>((const unsigned int*)d_in[i_b1],
                                (const unsigned int*)d_in[i_b2]);
    crf_repack_kernel<<<NSB / 256, 256>>>();
    crf_prep_kernel<<<(NT * NT + 255) / 256, 256>>>(trans, endt);
    crf_forward_kernel<<<BATCH / FW_WARPS, 32 * FW_WARPS>>>(em, startt);
    crf_score_kernel<<<BATCH / 8, 256>>>(em, startt, endt, trans);
    crf_reduce_kernel<<<1, BATCH>>>((float*)d_out);
}